// round 1
// baseline (speedup 1.0000x reference)
#include <cuda_runtime.h>
#include <cuda_bf16.h>
#include <mma.h>
#include <math.h>

using namespace nvcuda;

// Problem constants
#define T_STEPS 256
#define BATCH   25
#define VOCAB   32000
#define HID     1024
#define CLS     2
#define M_GEMM  (T_STEPS * BATCH)   // 6400

// ---------------- scratch (device globals: no allocation allowed) -------------
__device__ __align__(16) float g_Z[M_GEMM * HID];        // 26.2 MB: X @ W_xh
__device__ __align__(16) float g_h[2][BATCH * HID];      // double-buffered state
__device__ unsigned g_bar_cnt = 0;
__device__ volatile unsigned g_bar_gen = 0;

// ======================= Kernel 1: Z = X @ W_xh (tf32 WMMA) ===================
// M=6400, K=32000, N=1024. BM=128, BN=128, BK=32. 8 warps (2x4), warp tile 64x32.
#define BM 128
#define BN 128
#define BK 32
#define AS_LD 36
#define BS_LD 132

__global__ __launch_bounds__(256, 2) void gemm_xwxh_kernel(
    const float* __restrict__ A,   // X  [6400, 32000]
    const float* __restrict__ B,   // W_xh [32000, 1024]
    float* __restrict__ C)         // Z  [6400, 1024]
{
    __shared__ float As[BM][AS_LD];
    __shared__ float Bs[BK][BS_LD];

    const int tid = threadIdx.x;
    const int wid = tid >> 5;
    const int wm = wid >> 2;        // 0..1
    const int wn = wid & 3;         // 0..3
    const int m0 = blockIdx.y * BM;
    const int n0 = blockIdx.x * BN;

    wmma::fragment<wmma::accumulator, 16, 16, 8, float> acc[4][2];
#pragma unroll
    for (int i = 0; i < 4; i++)
#pragma unroll
        for (int j = 0; j < 2; j++)
            wmma::fill_fragment(acc[i][j], 0.0f);

    for (int k0 = 0; k0 < VOCAB; k0 += BK) {
        // load A tile: 128x32 = 1024 float4
#pragma unroll
        for (int i = 0; i < 4; i++) {
            int f = tid + i * 256;
            int row = f >> 3;           // /8 float4 per row
            int c4 = f & 7;
            float4 v = *reinterpret_cast<const float4*>(
                A + (size_t)(m0 + row) * VOCAB + k0 + c4 * 4);
            As[row][c4 * 4 + 0] = wmma::__float_to_tf32(v.x);
            As[row][c4 * 4 + 1] = wmma::__float_to_tf32(v.y);
            As[row][c4 * 4 + 2] = wmma::__float_to_tf32(v.z);
            As[row][c4 * 4 + 3] = wmma::__float_to_tf32(v.w);
        }
        // load B tile: 32x128 = 1024 float4
#pragma unroll
        for (int i = 0; i < 4; i++) {
            int f = tid + i * 256;
            int row = f >> 5;           // /32 float4 per row
            int c4 = f & 31;
            float4 v = *reinterpret_cast<const float4*>(
                B + (size_t)(k0 + row) * HID + n0 + c4 * 4);
            Bs[row][c4 * 4 + 0] = wmma::__float_to_tf32(v.x);
            Bs[row][c4 * 4 + 1] = wmma::__float_to_tf32(v.y);
            Bs[row][c4 * 4 + 2] = wmma::__float_to_tf32(v.z);
            Bs[row][c4 * 4 + 3] = wmma::__float_to_tf32(v.w);
        }
        __syncthreads();

#pragma unroll
        for (int kk = 0; kk < BK / 8; kk++) {
            wmma::fragment<wmma::matrix_a, 16, 16, 8, wmma::precision::tf32, wmma::row_major> af[4];
            wmma::fragment<wmma::matrix_b, 16, 16, 8, wmma::precision::tf32, wmma::row_major> bf[2];
#pragma unroll
            for (int i = 0; i < 4; i++)
                wmma::load_matrix_sync(af[i], &As[wm * 64 + i * 16][kk * 8], AS_LD);
#pragma unroll
            for (int j = 0; j < 2; j++)
                wmma::load_matrix_sync(bf[j], &Bs[kk * 8][wn * 32 + j * 16], BS_LD);
#pragma unroll
            for (int i = 0; i < 4; i++)
#pragma unroll
                for (int j = 0; j < 2; j++)
                    wmma::mma_sync(acc[i][j], af[i], bf[j], acc[i][j]);
        }
        __syncthreads();
    }

#pragma unroll
    for (int i = 0; i < 4; i++)
#pragma unroll
        for (int j = 0; j < 2; j++)
            wmma::store_matrix_sync(
                C + (size_t)(m0 + wm * 64 + i * 16) * HID + n0 + wn * 32 + j * 16,
                acc[i][j], HID, wmma::mem_row_major);
}

// ================= Kernel 2: recurrence + pool + fc + softmax =================
// 128 persistent blocks, each owns 8 output columns; grid barrier per step.
#define NB 128
#define CPB 8   // columns per block

__device__ __forceinline__ void gridbar() {
    __syncthreads();
    if (threadIdx.x == 0) {
        unsigned gen = g_bar_gen;
        __threadfence();
        if (atomicAdd(&g_bar_cnt, 1) == NB - 1) {
            atomicExch(&g_bar_cnt, 0);
            __threadfence();
            g_bar_gen = gen + 1;
        } else {
            while (g_bar_gen == gen) { __nanosleep(64); }
            __threadfence();
        }
    }
    __syncthreads();
}

__global__ __launch_bounds__(256, 1) void rnn_recurrence_kernel(
    const float* __restrict__ W_hh,   // [1024, 1024] (k, n)
    const float* __restrict__ b_h,    // [1024]
    const float* __restrict__ fc_w,   // [1024, 2]
    const float* __restrict__ fc_b,   // [2]
    float* __restrict__ out)          // [2]
{
    __shared__ float Ws[CPB][HID];    // W_hh column slice, transposed: [c][k]
    const int tid = threadIdx.x;
    const int wid = tid >> 5;
    const int lane = tid & 31;
    const int c0 = blockIdx.x * CPB;

    // load W_hh slice (transposed for conflict-free LDS.128)
    for (int i = tid; i < CPB * HID; i += 256) {
        int c = i >> 10, k = i & (HID - 1);
        Ws[c][k] = W_hh[k * HID + c0 + c];
    }
    // zero h buffer 0
    for (int i = tid; i < 200; i += 256)
        g_h[0][blockIdx.x * 200 + i] = 0.0f;
    gridbar();

    const float4* Ws4 = reinterpret_cast<const float4*>(&Ws[0][0]);

    for (int t = 0; t < T_STEPS; t++) {
        const int rb = t & 1, wb = rb ^ 1;
        const float4* h4 = reinterpret_cast<const float4*>(g_h[rb]);
        for (int b = wid; b < BATCH; b += 8) {
            float acc[CPB];
#pragma unroll
            for (int c = 0; c < CPB; c++) acc[c] = 0.0f;
            const float4* hrow = h4 + b * (HID / 4);
#pragma unroll
            for (int p = 0; p < 8; p++) {
                float4 hv = __ldcg(&hrow[p * 32 + lane]);
#pragma unroll
                for (int c = 0; c < CPB; c++) {
                    float4 wv = Ws4[c * 256 + p * 32 + lane];
                    acc[c] += hv.x * wv.x + hv.y * wv.y + hv.z * wv.z + hv.w * wv.w;
                }
            }
#pragma unroll
            for (int c = 0; c < CPB; c++) {
#pragma unroll
                for (int off = 16; off; off >>= 1)
                    acc[c] += __shfl_xor_sync(0xFFFFFFFFu, acc[c], off);
            }
            if (lane == 0) {
                const float* zrow = g_Z + ((size_t)t * BATCH + b) * HID + c0;
                float* hn = g_h[wb] + b * HID + c0;
#pragma unroll
                for (int c = 0; c < CPB; c++)
                    hn[c] = tanhf(zrow[c] + b_h[c0 + c] + acc[c]);
            }
        }
        gridbar();
    }

    // T even -> final state in g_h[0]. Block 0 finishes: pool, fc, softmax.
    if (blockIdx.x == 0) {
        __shared__ float red0[8], red1[8];
        float l0 = 0.0f, l1 = 0.0f;
        for (int n = tid; n < HID; n += 256) {
            float s = 0.0f;
#pragma unroll
            for (int b = 0; b < BATCH; b++)
                s += __ldcg(&g_h[0][b * HID + n]);
            float pooled = s * (1.0f / BATCH);
            l0 += pooled * fc_w[n * CLS + 0];
            l1 += pooled * fc_w[n * CLS + 1];
        }
#pragma unroll
        for (int off = 16; off; off >>= 1) {
            l0 += __shfl_xor_sync(0xFFFFFFFFu, l0, off);
            l1 += __shfl_xor_sync(0xFFFFFFFFu, l1, off);
        }
        if (lane == 0) { red0[wid] = l0; red1[wid] = l1; }
        __syncthreads();
        if (tid == 0) {
            float a = 0.0f, c = 0.0f;
#pragma unroll
            for (int w = 0; w < 8; w++) { a += red0[w]; c += red1[w]; }
            a += fc_b[0]; c += fc_b[1];
            float mx = fmaxf(a, c);
            float e0 = expf(a - mx), e1 = expf(c - mx);
            float inv = 1.0f / (e0 + e1);
            out[0] = e0 * inv;
            out[1] = e1 * inv;
        }
    }
}

// ================================ launcher ====================================
extern "C" void kernel_launch(void* const* d_in, const int* in_sizes, int n_in,
                              void* d_out, int out_size) {
    const float* X    = (const float*)d_in[0];
    const float* W_xh = (const float*)d_in[1];
    const float* W_hh = (const float*)d_in[2];
    const float* b_h  = (const float*)d_in[3];
    const float* fc_w = (const float*)d_in[4];
    const float* fc_b = (const float*)d_in[5];
    float* out = (float*)d_out;

    float* Z;
    cudaGetSymbolAddress((void**)&Z, g_Z);

    dim3 ggrid(HID / BN, M_GEMM / BM);     // (8, 50)
    gemm_xwxh_kernel<<<ggrid, 256>>>(X, W_xh, Z);
    rnn_recurrence_kernel<<<NB, 256>>>(W_hh, b_h, fc_w, fc_b, out);
}

// round 3
// speedup vs baseline: 1.7557x; 1.7557x over previous
#include <cuda_runtime.h>
#include <cuda_bf16.h>
#include <cstdint>
#include <math.h>

// Problem constants
#define T_STEPS 256
#define BATCH   25
#define VOCAB   32000
#define HID     1024
#define CLS     2
#define M_GEMM  (T_STEPS * BATCH)   // 6400

// ---------------- scratch (device globals: no allocation allowed) -------------
__device__ __align__(16) float g_Z[M_GEMM * HID];        // 26.2 MB: X @ W_xh
__device__ __align__(16) float g_h[2][BATCH * HID];      // double-buffered state
__device__ unsigned g_bar_cnt = 0;
__device__ volatile unsigned g_bar_gen = 0;

// ============================ helpers =========================================
__device__ __forceinline__ uint32_t smem_u32(const void* p) {
    uint32_t a;
    asm("{ .reg .u64 t; cvta.to.shared.u64 t, %1; cvt.u32.u64 %0, t; }" : "=r"(a) : "l"(p));
    return a;
}
__device__ __forceinline__ void cp_async16(uint32_t saddr, const void* g) {
    asm volatile("cp.async.cg.shared.global [%0], [%1], 16;\n" :: "r"(saddr), "l"(g));
}
__device__ __forceinline__ void cp_commit() {
    asm volatile("cp.async.commit_group;\n" ::: "memory");
}
__device__ __forceinline__ void cp_wait2() {
    asm volatile("cp.async.wait_group 2;\n" ::: "memory");
}
__device__ __forceinline__ void mma_tf32(float* d, const float* a, const float* b) {
    asm volatile(
        "mma.sync.aligned.m16n8k8.row.col.f32.tf32.tf32.f32 "
        "{%0,%1,%2,%3}, {%4,%5,%6,%7}, {%8,%9}, {%0,%1,%2,%3};\n"
        : "+f"(d[0]), "+f"(d[1]), "+f"(d[2]), "+f"(d[3])
        : "r"(__float_as_uint(a[0])), "r"(__float_as_uint(a[1])),
          "r"(__float_as_uint(a[2])), "r"(__float_as_uint(a[3])),
          "r"(__float_as_uint(b[0])), "r"(__float_as_uint(b[1])));
}

// ============== Kernel 1: Z = X @ W_xh via mma.sync tf32 ======================
// BM=128, BN=128, BK=32. 8 warps as 2(m) x 4(n), warp tile 64x32.
// 4-stage cp.async pipeline, 1 CTA/SM.
#define BM 128
#define BN 128
#define BK 32
#define STAGES 4
#define NITER (VOCAB / BK)           // 1000

#define A_PAD 36                     // floats per A row  (bank: 4g+t distinct)
#define B_PAD 136                    // floats per B row  (bank: 8t+g distinct)
#define A_FLOATS (BM * A_PAD)        // 4608  (18 KB)
#define B_FLOATS (BK * B_PAD)        // 4352  (17 KB)
#define STAGE_FLOATS (A_FLOATS + B_FLOATS)
#define GEMM_DYNSMEM (STAGES * STAGE_FLOATS * 4)

extern __shared__ float smem[];

__global__ __launch_bounds__(256, 1) void gemm_tc_kernel(
    const float* __restrict__ A,   // X    [6400, 32000] row-major (K contig)
    const float* __restrict__ B,   // W_xh [32000, 1024] row-major (N contig)
    float* __restrict__ C)         // Z    [6400, 1024]
{
    const int tid  = threadIdx.x;
    const int wid  = tid >> 5;
    const int lane = tid & 31;
    const int g    = lane >> 2;     // group id 0..7
    const int t    = lane & 3;      // thread-in-group 0..3
    const int wm   = wid >> 2;      // 0..1   (64-row slab)
    const int wn   = wid & 3;       // 0..3   (32-col slab)
    const int m0   = blockIdx.y * BM;
    const int n0   = blockIdx.x * BN;

    const uint32_t sbase = smem_u32(smem);

    // per-thread load coords (A: 128 rows x 8 chunks; B: 32 rows x 32 chunks)
    const int ar = tid >> 1;                // with i-offset below
    (void)ar;

    auto load_stage = [&](int it) {
        const int s = it & 3;
        const uint32_t abase = sbase + s * STAGE_FLOATS * 4;
        const uint32_t bbase = abase + A_FLOATS * 4;
        const float* Ag = A + (size_t)m0 * VOCAB + (size_t)it * BK;
        const float* Bg = B + (size_t)it * BK * HID + n0;
#pragma unroll
        for (int i = 0; i < 4; i++) {        // A: 1024 chunks of 16B
            int q = tid + i * 256;
            int r = q >> 3, c = q & 7;
            cp_async16(abase + (r * A_PAD + c * 4) * 4,
                       Ag + (size_t)r * VOCAB + c * 4);
        }
#pragma unroll
        for (int i = 0; i < 4; i++) {        // B: 1024 chunks of 16B
            int q = tid + i * 256;
            int r = q >> 5, c = q & 31;
            cp_async16(bbase + (r * B_PAD + c * 4) * 4,
                       Bg + (size_t)r * HID + c * 4);
        }
        cp_commit();
    };

    float acc[4][4][4];
#pragma unroll
    for (int i = 0; i < 4; i++)
#pragma unroll
        for (int j = 0; j < 4; j++)
#pragma unroll
            for (int k = 0; k < 4; k++) acc[i][j][k] = 0.0f;

    // prologue: 3 stages in flight
    load_stage(0); load_stage(1); load_stage(2);

#pragma unroll 1
    for (int it = 0; it < NITER; it++) {
        cp_wait2();
        __syncthreads();
        const int s = it & 3;
        const float* As = smem + s * STAGE_FLOATS;            // [128][36]
        const float* Bs = As + A_FLOATS;                      // [32][136]

#pragma unroll
        for (int k8 = 0; k8 < BK / 8; k8++) {
            // A fragments: 4 m-tiles
            float af[4][4];
#pragma unroll
            for (int mt = 0; mt < 4; mt++) {
                const int mrow = wm * 64 + mt * 16 + g;
                const float* ap = As + mrow * A_PAD + k8 * 8;
                af[mt][0] = ap[t];
                af[mt][1] = ap[8 * A_PAD + t];
                af[mt][2] = ap[t + 4];
                af[mt][3] = ap[8 * A_PAD + t + 4];
            }
            // B fragments: 4 n-tiles
            float bf[4][2];
#pragma unroll
            for (int nt = 0; nt < 4; nt++) {
                const int ncol = wn * 32 + nt * 8 + g;
                const float* bp = Bs + (k8 * 8 + t) * B_PAD + ncol;
                bf[nt][0] = bp[0];
                bf[nt][1] = bp[4 * B_PAD];
            }
#pragma unroll
            for (int mt = 0; mt < 4; mt++)
#pragma unroll
                for (int nt = 0; nt < 4; nt++)
                    mma_tf32(acc[mt][nt], af[mt], bf[nt]);
        }

        if (it + 3 < NITER) load_stage(it + 3);
    }

    // epilogue: direct register -> global stores (float2)
#pragma unroll
    for (int mt = 0; mt < 4; mt++) {
#pragma unroll
        for (int nt = 0; nt < 4; nt++) {
            const int r0 = m0 + wm * 64 + mt * 16 + g;
            const int c  = n0 + wn * 32 + nt * 8 + 2 * t;
            float2 v0 = make_float2(acc[mt][nt][0], acc[mt][nt][1]);
            float2 v1 = make_float2(acc[mt][nt][2], acc[mt][nt][3]);
            *reinterpret_cast<float2*>(C + (size_t)r0 * HID + c) = v0;
            *reinterpret_cast<float2*>(C + (size_t)(r0 + 8) * HID + c) = v1;
        }
    }
}

// ================= Kernel 2: recurrence + pool + fc + softmax =================
#define NB 128
#define CPB 8

__device__ __forceinline__ void gridbar() {
    __syncthreads();
    if (threadIdx.x == 0) {
        unsigned gen = g_bar_gen;
        __threadfence();
        if (atomicAdd(&g_bar_cnt, 1) == NB - 1) {
            atomicExch(&g_bar_cnt, 0);
            __threadfence();
            g_bar_gen = gen + 1;
        } else {
            while (g_bar_gen == gen) { __nanosleep(64); }
            __threadfence();
        }
    }
    __syncthreads();
}

__global__ __launch_bounds__(256, 1) void rnn_recurrence_kernel(
    const float* __restrict__ W_hh,   // [1024, 1024] (k, n)
    const float* __restrict__ b_h,    // [1024]
    const float* __restrict__ fc_w,   // [1024, 2]
    const float* __restrict__ fc_b,   // [2]
    float* __restrict__ out)          // [2]
{
    __shared__ float Ws[CPB][HID];
    const int tid = threadIdx.x;
    const int wid = tid >> 5;
    const int lane = tid & 31;
    const int c0 = blockIdx.x * CPB;

    for (int i = tid; i < CPB * HID; i += 256) {
        int c = i >> 10, k = i & (HID - 1);
        Ws[c][k] = W_hh[k * HID + c0 + c];
    }
    for (int i = tid; i < 200; i += 256)
        g_h[0][blockIdx.x * 200 + i] = 0.0f;
    gridbar();

    const float4* Ws4 = reinterpret_cast<const float4*>(&Ws[0][0]);

    for (int t = 0; t < T_STEPS; t++) {
        const int rb = t & 1, wb = rb ^ 1;
        const float4* h4 = reinterpret_cast<const float4*>(g_h[rb]);
        for (int b = wid; b < BATCH; b += 8) {
            float acc[CPB];
#pragma unroll
            for (int c = 0; c < CPB; c++) acc[c] = 0.0f;
            const float4* hrow = h4 + b * (HID / 4);
#pragma unroll
            for (int p = 0; p < 8; p++) {
                float4 hv = __ldcg(&hrow[p * 32 + lane]);
#pragma unroll
                for (int c = 0; c < CPB; c++) {
                    float4 wv = Ws4[c * 256 + p * 32 + lane];
                    acc[c] += hv.x * wv.x + hv.y * wv.y + hv.z * wv.z + hv.w * wv.w;
                }
            }
#pragma unroll
            for (int c = 0; c < CPB; c++) {
#pragma unroll
                for (int off = 16; off; off >>= 1)
                    acc[c] += __shfl_xor_sync(0xFFFFFFFFu, acc[c], off);
            }
            if (lane == 0) {
                const float* zrow = g_Z + ((size_t)t * BATCH + b) * HID + c0;
                float* hn = g_h[wb] + b * HID + c0;
#pragma unroll
                for (int c = 0; c < CPB; c++)
                    hn[c] = tanhf(zrow[c] + b_h[c0 + c] + acc[c]);
            }
        }
        gridbar();
    }

    if (blockIdx.x == 0) {
        __shared__ float red0[8], red1[8];
        float l0 = 0.0f, l1 = 0.0f;
        for (int n = tid; n < HID; n += 256) {
            float s = 0.0f;
#pragma unroll
            for (int b = 0; b < BATCH; b++)
                s += __ldcg(&g_h[0][b * HID + n]);
            float pooled = s * (1.0f / BATCH);
            l0 += pooled * fc_w[n * CLS + 0];
            l1 += pooled * fc_w[n * CLS + 1];
        }
#pragma unroll
        for (int off = 16; off; off >>= 1) {
            l0 += __shfl_xor_sync(0xFFFFFFFFu, l0, off);
            l1 += __shfl_xor_sync(0xFFFFFFFFu, l1, off);
        }
        if (lane == 0) { red0[wid] = l0; red1[wid] = l1; }
        __syncthreads();
        if (tid == 0) {
            float a = 0.0f, c = 0.0f;
#pragma unroll
            for (int w = 0; w < 8; w++) { a += red0[w]; c += red1[w]; }
            a += fc_b[0]; c += fc_b[1];
            float mx = fmaxf(a, c);
            float e0 = expf(a - mx), e1 = expf(c - mx);
            float inv = 1.0f / (e0 + e1);
            out[0] = e0 * inv;
            out[1] = e1 * inv;
        }
    }
}

// ================================ launcher ====================================
extern "C" void kernel_launch(void* const* d_in, const int* in_sizes, int n_in,
                              void* d_out, int out_size) {
    const float* X    = (const float*)d_in[0];
    const float* W_xh = (const float*)d_in[1];
    const float* W_hh = (const float*)d_in[2];
    const float* b_h  = (const float*)d_in[3];
    const float* fc_w = (const float*)d_in[4];
    const float* fc_b = (const float*)d_in[5];
    float* out = (float*)d_out;

    float* Z;
    cudaGetSymbolAddress((void**)&Z, g_Z);

    cudaFuncSetAttribute(gemm_tc_kernel,
                         cudaFuncAttributeMaxDynamicSharedMemorySize, GEMM_DYNSMEM);

    dim3 ggrid(HID / BN, M_GEMM / BM);         // (8, 50)
    gemm_tc_kernel<<<ggrid, 256, GEMM_DYNSMEM>>>(X, W_xh, Z);

    rnn_recurrence_kernel<<<NB, 256>>>(W_hh, b_h, fc_w, fc_b, out);
}